// round 7
// baseline (speedup 1.0000x reference)
#include <cuda_runtime.h>
#include <cuda_bf16.h>
#include <cstdint>

#define NN 100000   // nodes
#define HD 128      // hidden dim (= IN = OUT)
#define NR 8        // relations
#define NE 75000    // edges per relation
#define KP 136      // padded K stride (bf16 elems) for conflict-free fragment loads

// Scratch (allocation-free rule: device globals)
__device__ float g_h[(size_t)NN * HD];        // 51.2 MB
__device__ float g_h2[(size_t)NN * HD];       // 51.2 MB
__device__ float g_relout[(size_t)NN * HD];   // 51.2 MB
// Pre-split transposed weights B[n][k] (k-stride KP), bf16 hi/lo.
// Slot: 0=W_in, 1..8=W_rel[r], 9=W_self, 10=W_out.
__device__ __nv_bfloat16 g_whi[11 * 128 * KP];
__device__ __nv_bfloat16 g_wlo[11 * 128 * KP];

// m16n8k16 bf16 MMA, fp32 accumulate (baseline PTX, works on plain sm_100)
#define MMA16816(c, a0, a1, a2, a3, b0, b1) \
    asm volatile("mma.sync.aligned.m16n8k16.row.col.f32.bf16.bf16.f32 " \
                 "{%0,%1,%2,%3}, {%4,%5,%6,%7}, {%8,%9}, {%0,%1,%2,%3};" \
                 : "+f"((c)[0]), "+f"((c)[1]), "+f"((c)[2]), "+f"((c)[3]) \
                 : "r"(a0), "r"(a1), "r"(a2), "r"(a3), "r"(b0), "r"(b1))

// split two floats into packed bf16x2 hi and lo (lo = v - bf16(v))
__device__ __forceinline__ void split2(float a, float b, uint32_t& h, uint32_t& l) {
    __nv_bfloat16 ha = __float2bfloat16_rn(a);
    __nv_bfloat16 hb = __float2bfloat16_rn(b);
    __nv_bfloat162 hp; hp.x = ha; hp.y = hb;
    __nv_bfloat162 lp = __floats2bfloat162_rn(a - __bfloat162float(ha),
                                              b - __bfloat162float(hb));
    h = *reinterpret_cast<uint32_t*>(&hp);
    l = *reinterpret_cast<uint32_t*>(&lp);
}

// sOut word index for (row, col): stride 140, +4 word offset for col>=64 half
__device__ __forceinline__ int ow(int r, int c) {
    return r * 140 + c + ((c >> 6) << 2);
}

// ---------------------------------------------------------------------------
__global__ void k_zero() {
    size_t i = (size_t)blockIdx.x * blockDim.x + threadIdx.x;
    ((float4*)g_relout)[i] = make_float4(0.f, 0.f, 0.f, 0.f);
}

// ---------------------------------------------------------------------------
// k_prep: split weights into bf16 hi/lo, transposed: dst[n*KP + k] = W[k][n]
// ---------------------------------------------------------------------------
__global__ void k_prep(const float* __restrict__ W_in, const float* __restrict__ W_rel,
                       const float* __restrict__ W_self, const float* __restrict__ W_out) {
    int b = blockIdx.x;
    const float* src = (b == 0) ? W_in
                     : (b <= 8) ? W_rel + (size_t)(b - 1) * 16384
                     : (b == 9) ? W_self : W_out;
    __nv_bfloat16* dhi = g_whi + (size_t)b * 128 * KP;
    __nv_bfloat16* dlo = g_wlo + (size_t)b * 128 * KP;
    for (int idx = threadIdx.x; idx < 16384; idx += 256) {
        int n = idx >> 7, k = idx & 127;
        float v = src[k * 128 + n];
        __nv_bfloat16 hb = __float2bfloat16_rn(v);
        dhi[n * KP + k] = hb;
        dlo[n * KP + k] = __float2bfloat16_rn(v - __bfloat162float(hb));
    }
}

// ---------------------------------------------------------------------------
// Unified tensor-core GEMM kernel. 256 threads, 128-row x 128-col block tile.
// 8 warps in 2x4 grid: warp (w&1 -> 64-row group, w>>1 -> 32-col group);
// each warp computes 64x32 via 4 m16-frags x 4 n8-frags x 3 split terms.
// Mainloop smem reads per block: A 64KB*4 grp? -> A 64KB x2, B 64KB x... =
//   per warp: A 32KB + B 16KB = 48KB; x8 warps = 384KB per 128 rows
//   (vs 327KB per 64 rows previously -> ~41% reduction per output row).
// modes: 0: h=relu(x@W_in+b)       1: scatter (w*h[src])@W_r -> relout
//        2: h2=relu(h@W_self+b+relout)   3: out=h2@W_out+b
// SMEM: Whi/Wlo/Ahi/Alo = 4*34816 = 139264 B -> 1 CTA/SM.
// ---------------------------------------------------------------------------
__global__ void __launch_bounds__(256, 1)
k_gemm(int mode, int wslot,
       const float* __restrict__ Aext, const float* __restrict__ bias,
       const int* __restrict__ esrc, const int* __restrict__ edst,
       const float* __restrict__ ew, float* __restrict__ dext) {
    extern __shared__ char sm[];
    __nv_bfloat16* sWhi = (__nv_bfloat16*)sm;             // 34816 B
    __nv_bfloat16* sWlo = (__nv_bfloat16*)(sm + 34816);   // 34816 B
    __nv_bfloat16* sAhi = (__nv_bfloat16*)(sm + 69632);   // 34816 B
    __nv_bfloat16* sAlo = (__nv_bfloat16*)(sm + 104448);  // 34816 B
    float* sOut = (float*)sm;                             // 128 x 140 fp32 (reuse)
    __shared__ int sDst[128];

    const int tid = threadIdx.x;

    // stage weights (pre-split, pre-transposed): 64KB
    {
        int ws = wslot + ((mode == 1) ? (int)blockIdx.y : 0);
        const uint4* whi = (const uint4*)(g_whi + (size_t)ws * 128 * KP);
        const uint4* wlo = (const uint4*)(g_wlo + (size_t)ws * 128 * KP);
        uint4* dhi = (uint4*)sWhi;
        uint4* dlo = (uint4*)sWlo;
        for (int i = tid; i < 2176; i += 256) {
            dhi[i] = whi[i];
            dlo[i] = wlo[i];
        }
    }

    // stage A: 2 threads per row; thread (row=tid>>1, half=tid&1) covers 64 k
    const int row = tid >> 1, half = tid & 1;
    const int row0 = blockIdx.x * 128;
    float sc;
    const float* arow;
    if (mode == 1) {
        int e = row0 + row;
        bool valid = e < NE;
        int sidx = 0, dsti = 0;
        sc = 0.f;
        if (valid) {
            size_t eo = (size_t)blockIdx.y * NE + e;
            sidx = esrc[eo];
            sc = ew[eo];
            dsti = edst[eo];
        }
        if (half == 0) sDst[row] = dsti;
        arow = g_h + (size_t)sidx * HD;
    } else {
        int gr = row0 + row;
        bool valid = gr < NN;
        const float* As = (mode == 0) ? Aext : (mode == 2) ? g_h : g_h2;
        arow = As + (size_t)(valid ? gr : 0) * HD;
        sc = valid ? 1.f : 0.f;
    }
    {
        const float4* a4 = (const float4*)arow + half * 16;
        // destination: 8 uint4 (16 B each) covering 64 bf16 in hi and lo
        uint4* dh = (uint4*)((char*)sAhi + row * (KP * 2) + half * 128);
        uint4* dl = (uint4*)((char*)sAlo + row * (KP * 2) + half * 128);
#pragma unroll
        for (int i = 0; i < 8; i++) {
            float4 v0 = a4[2 * i], v1 = a4[2 * i + 1];
            v0.x *= sc; v0.y *= sc; v0.z *= sc; v0.w *= sc;
            v1.x *= sc; v1.y *= sc; v1.z *= sc; v1.w *= sc;
            uint4 hq, lq;
            split2(v0.x, v0.y, hq.x, lq.x);
            split2(v0.z, v0.w, hq.y, lq.y);
            split2(v1.x, v1.y, hq.z, lq.z);
            split2(v1.z, v1.w, hq.w, lq.w);
            dh[i] = hq;
            dl[i] = lq;
        }
    }
    __syncthreads();

    // MMA mainloop: warp computes 64 rows x 32 cols
    const int lane = tid & 31, warp = tid >> 5;
    const int R = 64 * (warp & 1), NB = 32 * (warp >> 1);
    const int fr = lane >> 2, q2 = (lane & 3) * 2;
    float acc[4][4][4];
#pragma unroll
    for (int m = 0; m < 4; m++)
#pragma unroll
        for (int n = 0; n < 4; n++)
            acc[m][n][0] = acc[m][n][1] = acc[m][n][2] = acc[m][n][3] = 0.f;

#pragma unroll
    for (int ks = 0; ks < 8; ks++) {
        const int k0 = ks * 16;
        uint32_t ah[4][4], al[4][4];
#pragma unroll
        for (int m = 0; m < 4; m++) {
            const __nv_bfloat16* ap = sAhi + (R + 16 * m + fr) * KP + k0 + q2;
            ah[m][0] = *(const uint32_t*)ap;
            ah[m][1] = *(const uint32_t*)(ap + 8 * KP);
            ah[m][2] = *(const uint32_t*)(ap + 8);
            ah[m][3] = *(const uint32_t*)(ap + 8 * KP + 8);
            const __nv_bfloat16* lp = sAlo + (R + 16 * m + fr) * KP + k0 + q2;
            al[m][0] = *(const uint32_t*)lp;
            al[m][1] = *(const uint32_t*)(lp + 8 * KP);
            al[m][2] = *(const uint32_t*)(lp + 8);
            al[m][3] = *(const uint32_t*)(lp + 8 * KP + 8);
        }
#pragma unroll
        for (int n = 0; n < 4; n++) {
            const __nv_bfloat16* bh = sWhi + (NB + 8 * n + fr) * KP + k0 + q2;
            const __nv_bfloat16* bl = sWlo + (NB + 8 * n + fr) * KP + k0 + q2;
            uint32_t bh0 = *(const uint32_t*)bh;
            uint32_t bh1 = *(const uint32_t*)(bh + 8);
            uint32_t bl0 = *(const uint32_t*)bl;
            uint32_t bl1 = *(const uint32_t*)(bl + 8);
#pragma unroll
            for (int m = 0; m < 4; m++) {
                MMA16816(acc[m][n], ah[m][0], ah[m][1], ah[m][2], ah[m][3], bh0, bh1);
                MMA16816(acc[m][n], ah[m][0], ah[m][1], ah[m][2], ah[m][3], bl0, bl1);
                MMA16816(acc[m][n], al[m][0], al[m][1], al[m][2], al[m][3], bh0, bh1);
            }
        }
    }

    // stage accumulators to smem (rows x stride-140 fp32), coalesced epilogue
    __syncthreads();  // weights + A dead; sOut reuses the whole smem
#pragma unroll
    for (int m = 0; m < 4; m++) {
#pragma unroll
        for (int n = 0; n < 4; n++) {
            int c = NB + 8 * n + q2;
            int r1 = R + 16 * m + fr;
            *(float2*)&sOut[ow(r1, c)]     = make_float2(acc[m][n][0], acc[m][n][1]);
            *(float2*)&sOut[ow(r1 + 8, c)] = make_float2(acc[m][n][2], acc[m][n][3]);
        }
    }
    __syncthreads();

    // epilogue: thread (row=tid>>1, half) handles cols half*64 .. +63
    const int cbase = half * 64;
    const float* srow = sOut + ow(row, cbase);
    if (mode == 1) {
        if (row0 + row < NE) {
            int d = sDst[row];
            float* op = g_relout + (size_t)d * HD + cbase;
#pragma unroll
            for (int i = 0; i < 16; i++) {
                float4 v = *(const float4*)(srow + i * 4);
                asm volatile("red.global.add.v4.f32 [%0], {%1,%2,%3,%4};"
                             :: "l"(op + i * 4), "f"(v.x), "f"(v.y), "f"(v.z), "f"(v.w)
                             : "memory");
            }
        }
    } else {
        int gr = row0 + row;
        if (gr < NN) {
            const float4* b4 = (const float4*)(bias + cbase);
            float4* o4 = (mode == 0) ? (float4*)(g_h  + (size_t)gr * HD + cbase)
                       : (mode == 2) ? (float4*)(g_h2 + (size_t)gr * HD + cbase)
                                     : (float4*)(dext + (size_t)gr * HD + cbase);
            const float4* ro4 = (const float4*)(g_relout + (size_t)gr * HD + cbase);
#pragma unroll
            for (int i = 0; i < 16; i++) {
                float4 v = *(const float4*)(srow + i * 4);
                float4 bb = b4[i];
                v.x += bb.x; v.y += bb.y; v.z += bb.z; v.w += bb.w;
                if (mode == 2) {
                    float4 rr = ro4[i];
                    v.x += rr.x; v.y += rr.y; v.z += rr.z; v.w += rr.w;
                }
                if (mode != 3) {
                    v.x = fmaxf(v.x, 0.f); v.y = fmaxf(v.y, 0.f);
                    v.z = fmaxf(v.z, 0.f); v.w = fmaxf(v.w, 0.f);
                }
                o4[i] = v;
            }
        }
    }
}

// ---------------------------------------------------------------------------
extern "C" void kernel_launch(void* const* d_in, const int* in_sizes, int n_in,
                              void* d_out, int out_size) {
    const float* x      = (const float*)d_in[0];
    const int*   esrc   = (const int*)d_in[1];
    const int*   edst   = (const int*)d_in[2];
    const float* ew     = (const float*)d_in[3];
    const float* W_in   = (const float*)d_in[4];
    const float* b_in   = (const float*)d_in[5];
    const float* W_rel  = (const float*)d_in[6];
    const float* W_self = (const float*)d_in[7];
    const float* b_self = (const float*)d_in[8];
    const float* W_out  = (const float*)d_in[9];
    const float* b_out  = (const float*)d_in[10];
    float* out = (float*)d_out;

    const int SMEM = 139264;  // Whi+Wlo+Ahi+Alo (sOut 128*140*4=71680 reuses it)

    static bool s_init = false;
    if (!s_init) {
        cudaFuncSetAttribute(k_gemm, cudaFuncAttributeMaxDynamicSharedMemorySize, SMEM);
        s_init = true;
    }

    // 0) weight split + transpose (tiny)
    k_prep<<<11, 256>>>(W_in, W_rel, W_self, W_out);

    // 1) zero rel_out
    k_zero<<<12500, 256>>>();

    // 2) h = relu(x @ W_in + b_in)
    k_gemm<<<782, 256, SMEM>>>(0, 0, x, b_in, nullptr, nullptr, nullptr, nullptr);

    // 3) rel_out += (w*h[src]) @ W_rel[r]  scatter, all relations
    k_gemm<<<dim3(586, NR), 256, SMEM>>>(1, 1, nullptr, nullptr, esrc, edst, ew, nullptr);

    // 4) h2 = relu(h @ W_self + b_self + rel_out)
    k_gemm<<<782, 256, SMEM>>>(2, 9, nullptr, b_self, nullptr, nullptr, nullptr, nullptr);

    // 5) out = h2 @ W_out + b_out
    k_gemm<<<782, 256, SMEM>>>(3, 10, nullptr, b_out, nullptr, nullptr, nullptr, out);
}